// round 11
// baseline (speedup 1.0000x reference)
#include <cuda_runtime.h>

// Problem constants
#define B_  256
#define T_  1024
#define I_  3
#define H_  128
#define O_  3

// ---------------------------------------------------------------------------
// Fast tanh: tanh(x) = 1 - 2/(1 + e^{2x}) via ex2.approx + rcp.approx.
// No clamp needed: ex2(+inf)=inf -> rcp(inf)=0 -> 1 (correct limit);
// ex2(-inf)=0 -> rcp(1)=1 -> -1 (correct). Measured end-to-end err ~5e-7.
// ---------------------------------------------------------------------------
__device__ __forceinline__ float fast_tanh(float x) {
    float e;
    asm("ex2.approx.f32 %0, %1;" : "=f"(e) : "f"(x * 2.885390081777927f));
    float rd;
    asm("rcp.approx.f32 %0, %1;" : "=f"(rd) : "f"(1.0f + e));
    return fmaf(-2.0f, rd, 1.0f);
}

// ---------------------------------------------------------------------------
// Recurrent kernel (proven R3 core): one block per batch, one thread per
// hidden unit, W_hh row j in 128 registers, double-buffered h in smem,
// one barrier per step, fused input projection with x prefetch.
// Tail shave: accumulator chain a0 is seeded with the input projection,
// removing one dependent FADD from the per-step serial tail.
// ---------------------------------------------------------------------------
__global__ void __launch_bounds__(H_, 2)
rnn_recurrent_kernel(const float* __restrict__ inputs,   // [B, T, I]
                     const float* __restrict__ W_ih,     // [H, I]
                     const float* __restrict__ W_hh,     // [H, H]
                     const float* __restrict__ b_ih,     // [H]
                     const float* __restrict__ b_hh,     // [H]
                     const float* __restrict__ h0,       // [1, H]
                     float* __restrict__ hiddens)        // [B, T, H]
{
    const int b = blockIdx.x;
    const int j = threadIdx.x;

    __shared__ float hbuf[2][H_];

    float w[H_];
    const float4* wrow = reinterpret_cast<const float4*>(W_hh + j * H_);
#pragma unroll
    for (int kk = 0; kk < H_ / 4; ++kk) {
        float4 v = wrow[kk];
        w[4 * kk + 0] = v.x;
        w[4 * kk + 1] = v.y;
        w[4 * kk + 2] = v.z;
        w[4 * kk + 3] = v.w;
    }

    const float wi0  = W_ih[j * I_ + 0];
    const float wi1  = W_ih[j * I_ + 1];
    const float wi2  = W_ih[j * I_ + 2];
    const float bias = b_ih[j] + b_hh[j];

    hbuf[0][j] = h0[j];
    __syncthreads();

    const float* inb  = inputs + (size_t)b * T_ * I_;
    float*       hout = hiddens + (size_t)b * T_ * H_;

    float x0 = inb[0], x1 = inb[1], x2 = inb[2];

    int cur = 0;
#pragma unroll 1
    for (int t = 0; t < T_; ++t) {
        // Seed chain 0 with the input projection (already-loaded x)
        float a0 = fmaf(x0, wi0, fmaf(x1, wi1, fmaf(x2, wi2, bias)));
        float a1 = 0.f, a2 = 0.f, a3 = 0.f;

        // prefetch next x (off the critical tail)
        {
            const int tn = (t + 1 < T_) ? (t + 1) : (T_ - 1);
            const float* nx = inb + tn * I_;
            x0 = nx[0]; x1 = nx[1]; x2 = nx[2];
        }

        const float4* h4 = reinterpret_cast<const float4*>(hbuf[cur]);
#pragma unroll
        for (int kk = 0; kk < H_ / 4; ++kk) {
            float4 hv = h4[kk];
            a0 = fmaf(hv.x, w[4 * kk + 0], a0);
            a1 = fmaf(hv.y, w[4 * kk + 1], a1);
            a2 = fmaf(hv.z, w[4 * kk + 2], a2);
            a3 = fmaf(hv.w, w[4 * kk + 3], a3);
        }
        const float acc = (a0 + a1) + (a2 + a3);

        const float hn = fast_tanh(acc);
        const int nxt = cur ^ 1;
        hbuf[nxt][j] = hn;
        hout[t * H_ + j] = hn;
        cur = nxt;
        __syncthreads();
    }
}

// ---------------------------------------------------------------------------
// Output projection, shallow-reduction layout.
// Warp handles 8 rows. lane = (row octet r8 = lane>>2, K-quarter q = lane&3).
// Lane covers k in [32q, 32q+32): its W_out quarter (3 outputs x 32 floats =
// 96 regs) is loaded once. Reduction is 2 SHFL levels within the 4-lane
// quarter (vs 5 levels across the warp). Lane q==0 writes the 3 outputs.
// ---------------------------------------------------------------------------
#define OP_THREADS 128
#define OP_ROWS_PER_BLOCK ((OP_THREADS / 32) * 8)   // 32 rows per block

__global__ void __launch_bounds__(OP_THREADS)
rnn_outproj_kernel(const float* __restrict__ hiddens, // [B*T, H]
                   const float* __restrict__ W_out,   // [O, H]
                   const float* __restrict__ b_out,   // [O]
                   float* __restrict__ out)           // [B*T, O]
{
    const int warp = threadIdx.x >> 5;
    const int lane = threadIdx.x & 31;
    const int r8   = lane >> 2;      // which of the 8 rows
    const int q    = lane & 3;       // K-quarter

    const size_t row = (size_t)blockIdx.x * OP_ROWS_PER_BLOCK + warp * 8 + r8;

    // W_out quarters -> registers (8 float4 per output row)
    float4 w0[8], w1[8], w2[8];
    {
        const float4* p0 = reinterpret_cast<const float4*>(W_out + 0 * H_ + q * 32);
        const float4* p1 = reinterpret_cast<const float4*>(W_out + 1 * H_ + q * 32);
        const float4* p2 = reinterpret_cast<const float4*>(W_out + 2 * H_ + q * 32);
#pragma unroll
        for (int i = 0; i < 8; ++i) { w0[i] = p0[i]; w1[i] = p1[i]; w2[i] = p2[i]; }
    }
    const float bo0 = b_out[0], bo1 = b_out[1], bo2 = b_out[2];

    // Load this lane's 32 h values (8 float4, coalesced across the quarter)
    const float4* hp = reinterpret_cast<const float4*>(hiddens + row * H_ + q * 32);
    float s0 = 0.f, s1 = 0.f, s2 = 0.f;
#pragma unroll
    for (int i = 0; i < 8; ++i) {
        const float4 hv = hp[i];
        s0 = fmaf(hv.x, w0[i].x, s0); s0 = fmaf(hv.y, w0[i].y, s0);
        s0 = fmaf(hv.z, w0[i].z, s0); s0 = fmaf(hv.w, w0[i].w, s0);
        s1 = fmaf(hv.x, w1[i].x, s1); s1 = fmaf(hv.y, w1[i].y, s1);
        s1 = fmaf(hv.z, w1[i].z, s1); s1 = fmaf(hv.w, w1[i].w, s1);
        s2 = fmaf(hv.x, w2[i].x, s2); s2 = fmaf(hv.y, w2[i].y, s2);
        s2 = fmaf(hv.z, w2[i].z, s2); s2 = fmaf(hv.w, w2[i].w, s2);
    }

    // 2-level reduction within the 4-lane quarter
    s0 += __shfl_down_sync(0xffffffffu, s0, 2);
    s1 += __shfl_down_sync(0xffffffffu, s1, 2);
    s2 += __shfl_down_sync(0xffffffffu, s2, 2);
    s0 += __shfl_down_sync(0xffffffffu, s0, 1);
    s1 += __shfl_down_sync(0xffffffffu, s1, 1);
    s2 += __shfl_down_sync(0xffffffffu, s2, 1);

    if (q == 0) {
        float* o = out + row * O_;
        o[0] = s0 + bo0;
        o[1] = s1 + bo1;
        o[2] = s2 + bo2;
    }
}

// ---------------------------------------------------------------------------
// kernel_launch
// ---------------------------------------------------------------------------
extern "C" void kernel_launch(void* const* d_in, const int* in_sizes, int n_in,
                              void* d_out, int out_size)
{
    const float* inputs = (const float*)d_in[0];
    const float* W_ih   = (const float*)d_in[1];
    const float* W_hh   = (const float*)d_in[2];
    const float* b_ih   = (const float*)d_in[3];
    const float* b_hh   = (const float*)d_in[4];
    const float* h0     = (const float*)d_in[5];
    const float* W_out  = (const float*)d_in[6];
    const float* b_out  = (const float*)d_in[7];

    float* out     = (float*)d_out;                        // [B,T,O]
    float* hiddens = (float*)d_out + (size_t)B_ * T_ * O_; // [B,T,H]

    rnn_recurrent_kernel<<<B_, H_>>>(inputs, W_ih, W_hh, b_ih, b_hh, h0, hiddens);

    const int rows   = B_ * T_;                               // 262144
    const int blocks = rows / OP_ROWS_PER_BLOCK;              // 8192 (exact)
    rnn_outproj_kernel<<<blocks, OP_THREADS>>>(hiddens, W_out, b_out, out);
}

// round 12
// speedup vs baseline: 1.1193x; 1.1193x over previous
#include <cuda_runtime.h>

// Problem constants
#define B_  256
#define T_  1024
#define I_  3
#define H_  128
#define O_  3

// ---------------------------------------------------------------------------
// Fast tanh: tanh(x) = 1 - 2/(1 + e^{2x}) via ex2.approx + rcp.approx.
// Limits are exact without clamping: ex2(+inf)=inf -> rcp -> 0 -> 1;
// ex2(-inf)=0 -> rcp(1)=1 -> -1. Measured end-to-end rel err ~5e-7.
// ---------------------------------------------------------------------------
__device__ __forceinline__ float fast_tanh(float x) {
    float e;
    asm("ex2.approx.f32 %0, %1;" : "=f"(e) : "f"(x * 2.885390081777927f));
    float rd;
    asm("rcp.approx.f32 %0, %1;" : "=f"(rd) : "f"(1.0f + e));
    return fmaf(-2.0f, rd, 1.0f);
}

// ---------------------------------------------------------------------------
// Recurrent kernel (proven R3 core) + anti-phase-lock skew.
// One block per batch, one thread per hidden unit, W_hh row j in 128
// registers, double-buffered h in smem, one barrier per step, fused input
// projection with x prefetch.
// Blocks bid and bid+148 co-reside on one SM with identical instruction
// streams -> lockstep -> their serial tanh/barrier tails coincide and the
// FMA pipe idles twice per step. A one-time ~300-cycle delay for the
// second-slot blocks (bid >= 148) offsets the phases so one block's FMA
// region covers the other's tail. The offset self-maintains (equal step
// durations).
// ---------------------------------------------------------------------------
__global__ void __launch_bounds__(H_, 2)
rnn_recurrent_kernel(const float* __restrict__ inputs,   // [B, T, I]
                     const float* __restrict__ W_ih,     // [H, I]
                     const float* __restrict__ W_hh,     // [H, H]
                     const float* __restrict__ b_ih,     // [H]
                     const float* __restrict__ b_hh,     // [H]
                     const float* __restrict__ h0,       // [1, H]
                     float* __restrict__ hiddens)        // [B, T, H]
{
    const int b = blockIdx.x;
    const int j = threadIdx.x;

    __shared__ float hbuf[2][H_];

    float w[H_];
    const float4* wrow = reinterpret_cast<const float4*>(W_hh + j * H_);
#pragma unroll
    for (int kk = 0; kk < H_ / 4; ++kk) {
        float4 v = wrow[kk];
        w[4 * kk + 0] = v.x;
        w[4 * kk + 1] = v.y;
        w[4 * kk + 2] = v.z;
        w[4 * kk + 3] = v.w;
    }

    const float wi0  = W_ih[j * I_ + 0];
    const float wi1  = W_ih[j * I_ + 1];
    const float wi2  = W_ih[j * I_ + 2];
    const float bias = b_ih[j] + b_hh[j];

    hbuf[0][j] = h0[j];

    // Anti-phase-lock skew: ~300 cycles of dependent FMAs for the block in
    // the SM's second occupancy slot. Result can never satisfy the guard,
    // but the compiler must compute it.
    if (b >= 148) {
        float d = bias * 1e-30f;
#pragma unroll 1
        for (int i = 0; i < 75; ++i)
            d = fmaf(d, 0.999f, 1e-30f);
        if (d > 1e10f) hbuf[0][0] = d;   // never taken
    }
    __syncthreads();

    const float* inb  = inputs + (size_t)b * T_ * I_;
    float*       hout = hiddens + (size_t)b * T_ * H_;

    float x0 = inb[0], x1 = inb[1], x2 = inb[2];

    int cur = 0;
#pragma unroll 1
    for (int t = 0; t < T_; ++t) {
        // Seed chain 0 with the input projection (already-loaded x)
        float a0 = fmaf(x0, wi0, fmaf(x1, wi1, fmaf(x2, wi2, bias)));
        float a1 = 0.f, a2 = 0.f, a3 = 0.f;

        // prefetch next x (off the critical tail)
        {
            const int tn = (t + 1 < T_) ? (t + 1) : (T_ - 1);
            const float* nx = inb + tn * I_;
            x0 = nx[0]; x1 = nx[1]; x2 = nx[2];
        }

        const float4* h4 = reinterpret_cast<const float4*>(hbuf[cur]);
#pragma unroll
        for (int kk = 0; kk < H_ / 4; ++kk) {
            float4 hv = h4[kk];
            a0 = fmaf(hv.x, w[4 * kk + 0], a0);
            a1 = fmaf(hv.y, w[4 * kk + 1], a1);
            a2 = fmaf(hv.z, w[4 * kk + 2], a2);
            a3 = fmaf(hv.w, w[4 * kk + 3], a3);
        }
        const float acc = (a0 + a1) + (a2 + a3);

        const float hn = fast_tanh(acc);
        const int nxt = cur ^ 1;
        hbuf[nxt][j] = hn;
        hout[t * H_ + j] = hn;
        cur = nxt;
        __syncthreads();
    }
}

// ---------------------------------------------------------------------------
// Output projection: proven R2 config (measured 29.98us).
// One warp per 4 rows, full-warp float4 dot + 5-level SHFL reduction.
// ---------------------------------------------------------------------------
#define ROWS_PER_WARP 4

__global__ void __launch_bounds__(256)
rnn_outproj_kernel(const float* __restrict__ hiddens, // [B*T, H]
                   const float* __restrict__ W_out,   // [O, H]
                   const float* __restrict__ b_out,   // [O]
                   float* __restrict__ out)           // [B*T, O]
{
    const int warp = (blockIdx.x * blockDim.x + threadIdx.x) >> 5;
    const int lane = threadIdx.x & 31;
    const int row0 = warp * ROWS_PER_WARP;
    if (row0 >= B_ * T_) return;

    const float4 w0 = reinterpret_cast<const float4*>(W_out + 0 * H_)[lane];
    const float4 w1 = reinterpret_cast<const float4*>(W_out + 1 * H_)[lane];
    const float4 w2 = reinterpret_cast<const float4*>(W_out + 2 * H_)[lane];
    const float bo0 = b_out[0], bo1 = b_out[1], bo2 = b_out[2];

    // Issue all row loads up front (MLP)
    float4 hv[ROWS_PER_WARP];
#pragma unroll
    for (int r = 0; r < ROWS_PER_WARP; ++r)
        hv[r] = reinterpret_cast<const float4*>(hiddens + (size_t)(row0 + r) * H_)[lane];

#pragma unroll
    for (int r = 0; r < ROWS_PER_WARP; ++r) {
        float s0 = hv[r].x * w0.x + hv[r].y * w0.y + hv[r].z * w0.z + hv[r].w * w0.w;
        float s1 = hv[r].x * w1.x + hv[r].y * w1.y + hv[r].z * w1.z + hv[r].w * w1.w;
        float s2 = hv[r].x * w2.x + hv[r].y * w2.y + hv[r].z * w2.z + hv[r].w * w2.w;
#pragma unroll
        for (int off = 16; off > 0; off >>= 1) {
            s0 += __shfl_down_sync(0xffffffffu, s0, off);
            s1 += __shfl_down_sync(0xffffffffu, s1, off);
            s2 += __shfl_down_sync(0xffffffffu, s2, off);
        }
        if (lane == 0) {
            float* o = out + (size_t)(row0 + r) * O_;
            o[0] = s0 + bo0;
            o[1] = s1 + bo1;
            o[2] = s2 + bo2;
        }
    }
}

// ---------------------------------------------------------------------------
// kernel_launch
// ---------------------------------------------------------------------------
extern "C" void kernel_launch(void* const* d_in, const int* in_sizes, int n_in,
                              void* d_out, int out_size)
{
    const float* inputs = (const float*)d_in[0];
    const float* W_ih   = (const float*)d_in[1];
    const float* W_hh   = (const float*)d_in[2];
    const float* b_ih   = (const float*)d_in[3];
    const float* b_hh   = (const float*)d_in[4];
    const float* h0     = (const float*)d_in[5];
    const float* W_out  = (const float*)d_in[6];
    const float* b_out  = (const float*)d_in[7];

    float* out     = (float*)d_out;                        // [B,T,O]
    float* hiddens = (float*)d_out + (size_t)B_ * T_ * O_; // [B,T,H]

    rnn_recurrent_kernel<<<B_, H_>>>(inputs, W_ih, W_hh, b_ih, b_hh, h0, hiddens);

    const int rows = B_ * T_;
    const int rows_per_block = (256 / 32) * ROWS_PER_WARP;   // 32
    const int blocks = (rows + rows_per_block - 1) / rows_per_block;  // 8192
    rnn_outproj_kernel<<<blocks, 256>>>(hiddens, W_out, b_out, out);
}